// round 16
// baseline (speedup 1.0000x reference)
#include <cuda_runtime.h>

// ImprovedRNN (LSTM) B=256, T=1024, I=64, H=25, O=64, fp32.
// Gate order (PyTorch): i, f, g, o = rows 0..24, 25..49, 50..74, 75..99.
//
// R15: SINGLE fused kernel (no streams -> trivially graph-capturable):
//   CTAs 0..127   : persistent gates producers, CHUNK-MAJOR (finish chunk 0
//                   first, ~4-6us), publish via threadfence+atomicAdd.
//   CTAs 128..191 : 4 independent lstm warps per CTA (one batch each),
//                   R10 step body, spin-wait on chunk counters only at
//                   64-step boundaries. Producers stay ~3x ahead.
//   All 192 CTAs co-resident in wave 1 -> pipelined, deadlock-free
//   (producers never wait; consumer spins are bounded).
// fc_kernel afterwards (measured ~40us).

static constexpr int Bb = 256;
static constexpr int Tt = 1024;
static constexpr int Ii = 64;
static constexpr int Hh = 25;
static constexpr int Gg = 4 * Hh;   // 100
static constexpr int Oo = 64;
static constexpr int ROWS = Bb * Tt;

static constexpr int CHUNK_T    = 64;              // steps per chunk
static constexpr int N_CHUNKS   = Tt / CHUNK_T;    // 16
static constexpr int PROD_CTAS  = 128;             // producer CTAs (persistent)
static constexpr int CONS_CTAS  = Bb / 4;          // 64 consumer CTAs (4 warps)
static constexpr int GRID       = PROD_CTAS + CONS_CTAS;   // 192

typedef unsigned long long ull;

// Scratch (device globals: allocation APIs are forbidden).
__device__ float g_gates[(size_t)ROWS * Gg];   // ~100 MB
__device__ float g_hs[(size_t)ROWS * Hh];      // ~25 MB
__device__ int   g_chunk_cnt[N_CHUNKS];        // producer arrival counters

// ---- packed f32x2 helpers (sm_100+; ptxas never auto-fuses these) ----
__device__ __forceinline__ ull ffma2(ull a, ull b, ull c) {
    ull d;
    asm("fma.rn.f32x2 %0, %1, %2, %3;" : "=l"(d) : "l"(a), "l"(b), "l"(c));
    return d;
}
__device__ __forceinline__ ull fadd2(ull a, ull b) {
    ull d;
    asm("add.rn.f32x2 %0, %1, %2;" : "=l"(d) : "l"(a), "l"(b));
    return d;
}
__device__ __forceinline__ ull pack2(float lo, float hi) {
    ull r;
    asm("mov.b64 %0, {%1, %2};" : "=l"(r) : "f"(lo), "f"(hi));
    return r;
}
__device__ __forceinline__ float2 unpack2(ull v) {
    float2 r;
    asm("mov.b64 {%0, %1}, %2;" : "=f"(r.x), "=f"(r.y) : "l"(v));
    return r;
}
__device__ __forceinline__ float tanh_fast(float x) {
    float r;
    asm("tanh.approx.f32 %0, %1;" : "=f"(r) : "f"(x));
    return r;
}
// sigmoid(x) = 0.5*tanh(0.5x) + 0.5 — one MUFU instead of EX2+RCP.
__device__ __forceinline__ float sigmoid_fast(float x) {
    return fmaf(tanh_fast(0.5f * x), 0.5f, 0.5f);
}

// ---------------------------------------------------------------------------
// init: zero the chunk counters (runs before the fused kernel every replay).
// ---------------------------------------------------------------------------
__global__ void init_kernel() {
    if (threadIdx.x < N_CHUNKS) g_chunk_cnt[threadIdx.x] = 0;
}

// ---------------------------------------------------------------------------
// Consumer-side wait: spin until chunk c fully published. Bounded so a
// logic bug produces wrong results (visible) instead of a hang. Per-warp.
// ---------------------------------------------------------------------------
__device__ __forceinline__ void wait_chunk(int c) {
    if ((threadIdx.x & 31) == 0) {
        int iters = 0;
        while (((volatile int*)g_chunk_cnt)[c] < PROD_CTAS) {
            __nanosleep(64);
            if (++iters > 50000000) break;   // safety bail
        }
    }
    __syncwarp();
    __threadfence();   // acquire: order gate reads after counter observation
}

// ---------------------------------------------------------------------------
// Fused producer/consumer kernel.
// ---------------------------------------------------------------------------
__global__ __launch_bounds__(128, 1) void fused_kernel(
    const float* __restrict__ x,
    const float* __restrict__ W_ih,
    const float* __restrict__ b_ih,
    const float* __restrict__ b_hh,
    const float* __restrict__ W_hh)
{
    const int tid = threadIdx.x;

    if (blockIdx.x < PROD_CTAS) {
        // =================== PRODUCER: chunk-major gates GEMM ===============
        __shared__ ull Wif2[Hh * Ii];    // {W_ih[j][i], W_ih[25+j][i]}
        __shared__ ull Wgo2[Hh * Ii];    // {W_ih[50+j][i], W_ih[75+j][i]}
        __shared__ float4 bsh[Hh];

        for (int idx = tid; idx < Hh * Ii; idx += 128) {
            const int j = idx >> 6, i = idx & 63;
            Wif2[idx] = pack2(W_ih[j * Ii + i],        W_ih[(25 + j) * Ii + i]);
            Wgo2[idx] = pack2(W_ih[(50 + j) * Ii + i], W_ih[(75 + j) * Ii + i]);
        }
        if (tid < Hh)
            bsh[tid] = make_float4(b_ih[tid]      + b_hh[tid],
                                   b_ih[25 + tid] + b_hh[25 + tid],
                                   b_ih[50 + tid] + b_hh[50 + tid],
                                   b_ih[75 + tid] + b_hh[75 + tid]);
        __syncthreads();

        // This thread's (batch, t-within-chunk) slot, fixed across chunks.
        const int idx16 = blockIdx.x * 128 + tid;     // [0, 16384)
        const int brow  = idx16 >> 6;                 // batch     [0, 256)
        const int tt    = idx16 & 63;                 // t in chunk [0, 64)

#pragma unroll 1
        for (int chunk = 0; chunk < N_CHUNKS; ++chunk) {
            const size_t row = (size_t)brow * Tt + (size_t)chunk * CHUNK_T + tt;

            ull xx[Ii];
            const float4* xp = (const float4*)(x + row * Ii);
#pragma unroll
            for (int i4 = 0; i4 < Ii / 4; ++i4) {
                const float4 v = xp[i4];
                xx[4 * i4 + 0] = pack2(v.x, v.x);
                xx[4 * i4 + 1] = pack2(v.y, v.y);
                xx[4 * i4 + 2] = pack2(v.z, v.z);
                xx[4 * i4 + 3] = pack2(v.w, v.w);
            }

            float4* gout = (float4*)(g_gates + row * Gg);

#pragma unroll 1
            for (int j = 0; j < Hh; ++j) {
                ull aif0 = 0ull, aif1 = 0ull, ago0 = 0ull, ago1 = 0ull;
                const ull* wi = &Wif2[j * Ii];
                const ull* wg = &Wgo2[j * Ii];
#pragma unroll
                for (int i = 0; i < Ii; i += 2) {
                    aif0 = ffma2(wi[i],     xx[i],     aif0);
                    aif1 = ffma2(wi[i + 1], xx[i + 1], aif1);
                    ago0 = ffma2(wg[i],     xx[i],     ago0);
                    ago1 = ffma2(wg[i + 1], xx[i + 1], ago1);
                }
                const float2 fi0 = unpack2(aif0), fi1 = unpack2(aif1);
                const float2 fg0 = unpack2(ago0), fg1 = unpack2(ago1);
                const float4 bb = bsh[j];
                gout[j] = make_float4(fi0.x + fi1.x + bb.x,
                                      fi0.y + fi1.y + bb.y,
                                      fg0.x + fg1.x + bb.z,
                                      fg0.y + fg1.y + bb.w);
            }

            // Publish chunk: stores visible, then arrive on counter.
            __threadfence();
            __syncthreads();
            if (tid == 0) atomicAdd(&g_chunk_cnt[chunk], 1);
        }
    } else {
        // =================== CONSUMER: LSTM recurrence ======================
        // 4 independent warps per CTA, one batch element each.
        const int wid  = tid >> 5;
        const int lane = tid & 31;
        const int b    = (blockIdx.x - PROD_CTAS) * 4 + wid;

        const int jc = (lane < Hh) ? lane : (Hh - 1);
        const bool act = (lane < Hh);

        // Recurrent weights packed (i,f)/(g,o) per k.
        ull wif[Hh], wgo[Hh];
#pragma unroll
        for (int k = 0; k < Hh; ++k) {
            wif[k] = pack2(W_hh[jc * Hh + k],        W_hh[(25 + jc) * Hh + k]);
            wgo[k] = pack2(W_hh[(50 + jc) * Hh + k], W_hh[(75 + jc) * Hh + k]);
        }

        const float4* gp = (const float4*)g_gates + (size_t)b * Tt * Hh + jc;
        float* hp = g_hs + (size_t)b * Tt * Hh + lane;

        float h = 0.0f, c = 0.0f;

        // Chunk 0 must be published before the initial queue fill (t=0..3).
        wait_chunk(0);

        float4 q[4];
#pragma unroll
        for (int d = 0; d < 4; ++d) q[d] = gp[(size_t)d * Hh];

#pragma unroll 1
        for (int t = 0; t < Tt; t += 4) {
            // Prefetches in this block reach t+7; wait before crossing.
            if ((t & 63) == 60 && t + CHUNK_T < Tt) wait_chunk((t >> 6) + 1);

#pragma unroll
            for (int u = 0; u < 4; ++u) {
                const float4 g = q[u];
                if (t + 4 + u < Tt) q[u] = gp[(size_t)(t + 4 + u) * Hh];

                // h @ W_hh^T : 4-way split accumulators per gate pair.
                ull a0 = 0ull, a1 = 0ull, a2 = 0ull, a3 = 0ull;   // (i,f)
                ull d0 = 0ull, d1 = 0ull, d2 = 0ull, d3 = 0ull;   // (g,o)
#pragma unroll
                for (int k = 0; k < Hh; ++k) {
                    const float hk = __shfl_sync(0xffffffffu, h, k);
                    const ull h2 = pack2(hk, hk);
                    switch (k & 3) {
                        case 0: a0 = ffma2(wif[k], h2, a0); d0 = ffma2(wgo[k], h2, d0); break;
                        case 1: a1 = ffma2(wif[k], h2, a1); d1 = ffma2(wgo[k], h2, d1); break;
                        case 2: a2 = ffma2(wif[k], h2, a2); d2 = ffma2(wgo[k], h2, d2); break;
                        default: a3 = ffma2(wif[k], h2, a3); d3 = ffma2(wgo[k], h2, d3); break;
                    }
                }
                const ull aif = fadd2(fadd2(a0, a1), fadd2(a2, a3));
                const ull ago = fadd2(fadd2(d0, d1), fadd2(d2, d3));

                const float2 fif = unpack2(aif);
                const float2 fgo = unpack2(ago);
                const float iv = sigmoid_fast(g.x + fif.x);
                const float fv = sigmoid_fast(g.y + fif.y);
                const float gv = tanh_fast   (g.z + fgo.x);
                const float ov = sigmoid_fast(g.w + fgo.y);

                c = fv * c + iv * gv;
                const float hn = ov * tanh_fast(c);
                h = act ? hn : 0.0f;
                if (act) hp[(size_t)(t + u) * Hh] = hn;   // predicated store
            }
        }
    }
}

// ---------------------------------------------------------------------------
// Phase 3: out[row][o] = b_fc[o] + sum_k hs[row][k] * W_fc[o][k]
// ---------------------------------------------------------------------------
__global__ __launch_bounds__(128) void fc_kernel(
    const float* __restrict__ W_fc,
    const float* __restrict__ b_fc,
    float* __restrict__ out)
{
    __shared__ ull Wt2[Hh * (Oo / 2)];   // {W_fc[2p][k], W_fc[2p+1][k]}
    __shared__ ull bsh2[Oo / 2];

    const int tid = threadIdx.x;
    for (int idx = tid; idx < Hh * (Oo / 2); idx += 128) {
        const int k = idx / (Oo / 2);
        const int p = idx % (Oo / 2);
        Wt2[idx] = pack2(W_fc[(2 * p) * Hh + k], W_fc[(2 * p + 1) * Hh + k]);
    }
    if (tid < Oo / 2) bsh2[tid] = pack2(b_fc[2 * tid], b_fc[2 * tid + 1]);
    __syncthreads();

    const size_t row = (size_t)blockIdx.x * 128 + tid;
    const float* hp = g_hs + row * Hh;

    float hv[Hh];
#pragma unroll
    for (int k = 0; k < Hh; ++k) hv[k] = hp[k];

    ull acc[Oo / 2];
#pragma unroll
    for (int p = 0; p < Oo / 2; ++p) acc[p] = bsh2[p];

#pragma unroll 1
    for (int k = 0; k < Hh; ++k) {
        const ull h2 = pack2(hv[k], hv[k]);
        const ull* wv = &Wt2[k * (Oo / 2)];
#pragma unroll
        for (int p = 0; p < Oo / 2; ++p)
            acc[p] = ffma2(wv[p], h2, acc[p]);
    }

    float4* op = (float4*)(out + row * Oo);
#pragma unroll
    for (int p4 = 0; p4 < Oo / 4; ++p4) {
        const float2 a = unpack2(acc[2 * p4]);
        const float2 b = unpack2(acc[2 * p4 + 1]);
        op[p4] = make_float4(a.x, a.y, b.x, b.y);
    }
}

// ---------------------------------------------------------------------------
extern "C" void kernel_launch(void* const* d_in, const int* in_sizes, int n_in,
                              void* d_out, int out_size)
{
    const float* x    = (const float*)d_in[0];
    const float* W_ih = (const float*)d_in[1];
    const float* W_hh = (const float*)d_in[2];
    const float* b_ih = (const float*)d_in[3];
    const float* b_hh = (const float*)d_in[4];
    const float* W_fc = (const float*)d_in[5];
    const float* b_fc = (const float*)d_in[6];
    float* out = (float*)d_out;

    init_kernel<<<1, 32>>>();
    fused_kernel<<<GRID, 128>>>(x, W_ih, b_ih, b_hh, W_hh);
    fc_kernel<<<ROWS / 128, 128>>>(W_fc, b_fc, out);
}